// round 3
// baseline (speedup 1.0000x reference)
#include <cuda_runtime.h>

// Problem constants
#define T_LEN 2048
#define BATCH 32
#define DIM   256
#define HID   256
#define G3    768   // 3H (weight leading dim)
#define N2    512   // we only need the first 2H columns (c_pre is dead)

#define SCAN_BLOCKS 64

// ---------------------------------------------------------------------------
// Device scratch (no allocations allowed -> __device__ globals)
// ---------------------------------------------------------------------------
__device__ float g_X[(size_t)T_LEN * N2 * BATCH];    // precomputed x@Wih + b, layout [t][c(512)][b(32)]
__device__ float g_out0[(size_t)T_LEN * BATCH * HID]; // layer-0 output, layout [t][b][h]
__device__ float g_h[2][HID * BATCH];                 // double-buffered hidden, layout [k][r] (k = h col)
__device__ unsigned g_bar_cnt = 0;
__device__ volatile unsigned g_bar_gen = 0;

// ---------------------------------------------------------------------------
// Sense-reversing grid barrier (all blocks co-resident: 64 <= 148 SMs)
// ---------------------------------------------------------------------------
__device__ __forceinline__ void grid_barrier(int nblk) {
    __threadfence();          // publish this thread's global writes
    __syncthreads();
    if (threadIdx.x == 0) {
        unsigned gen = g_bar_gen;
        if (atomicAdd(&g_bar_cnt, 1u) == (unsigned)(nblk - 1)) {
            atomicExch(&g_bar_cnt, 0u);
            __threadfence();
            g_bar_gen = gen + 1u;
        } else {
            while (g_bar_gen == gen) { }
        }
        __threadfence();
    }
    __syncthreads();
}

// ---------------------------------------------------------------------------
// X = A @ W[:, :512] + bias[:512]
// A: [65536, 256] row-major (input_ flattened [t*32+b][d], or g_out0)
// W: [256, 768] row-major, we use columns [0, 512)
// Output into g_X with layout [t][c][b] so the scan reads coalesced.
// Tiling: BM=64 (2 timesteps), BN=64, BK=32, 256 threads, 4x4 per thread.
// ---------------------------------------------------------------------------
__global__ __launch_bounds__(256, 1) void gemm_x_kernel(
    const float* __restrict__ A_in,
    const float* __restrict__ W,
    const float* __restrict__ bias)
{
    __shared__ float As[32][65];   // transposed [k][m], pad 65 -> conflict-free stores
    __shared__ float Bs[32][64];

    const float* A = A_in ? A_in : g_out0;

    const int tid = threadIdx.x;
    const int m0  = blockIdx.x * 64;
    const int n0  = blockIdx.y * 64;
    const int tx  = tid & 15;        // row group: rows tx*4 .. tx*4+3
    const int ty  = tid >> 4;        // col group: cols ty*4 .. ty*4+3
    const int ar  = tid >> 2;        // A load: row 0..63
    const int ak  = (tid & 3) * 8;   // A load: k offset (8 floats)
    const int bk  = tid >> 3;        // B load: k row 0..31
    const int bc  = (tid & 7) * 8;   // B load: col offset (8 floats)

    float acc[4][4];
#pragma unroll
    for (int i = 0; i < 4; i++)
#pragma unroll
        for (int j = 0; j < 4; j++) acc[i][j] = 0.f;

    for (int k0 = 0; k0 < DIM; k0 += 32) {
        float4 a0  = *(const float4*)&A[(size_t)(m0 + ar) * DIM + k0 + ak];
        float4 a1  = *(const float4*)&A[(size_t)(m0 + ar) * DIM + k0 + ak + 4];
        float4 b0v = *(const float4*)&W[(size_t)(k0 + bk) * G3 + n0 + bc];
        float4 b1v = *(const float4*)&W[(size_t)(k0 + bk) * G3 + n0 + bc + 4];

        As[ak + 0][ar] = a0.x; As[ak + 1][ar] = a0.y;
        As[ak + 2][ar] = a0.z; As[ak + 3][ar] = a0.w;
        As[ak + 4][ar] = a1.x; As[ak + 5][ar] = a1.y;
        As[ak + 6][ar] = a1.z; As[ak + 7][ar] = a1.w;
        *(float4*)&Bs[bk][bc]     = b0v;
        *(float4*)&Bs[bk][bc + 4] = b1v;
        __syncthreads();

#pragma unroll
        for (int kk = 0; kk < 32; kk++) {
            const float av0 = As[kk][tx * 4 + 0];
            const float av1 = As[kk][tx * 4 + 1];
            const float av2 = As[kk][tx * 4 + 2];
            const float av3 = As[kk][tx * 4 + 3];
            const float4 bq = *(const float4*)&Bs[kk][ty * 4];
            acc[0][0] = fmaf(av0, bq.x, acc[0][0]);
            acc[1][0] = fmaf(av1, bq.x, acc[1][0]);
            acc[2][0] = fmaf(av2, bq.x, acc[2][0]);
            acc[3][0] = fmaf(av3, bq.x, acc[3][0]);
            acc[0][1] = fmaf(av0, bq.y, acc[0][1]);
            acc[1][1] = fmaf(av1, bq.y, acc[1][1]);
            acc[2][1] = fmaf(av2, bq.y, acc[2][1]);
            acc[3][1] = fmaf(av3, bq.y, acc[3][1]);
            acc[0][2] = fmaf(av0, bq.z, acc[0][2]);
            acc[1][2] = fmaf(av1, bq.z, acc[1][2]);
            acc[2][2] = fmaf(av2, bq.z, acc[2][2]);
            acc[3][2] = fmaf(av3, bq.z, acc[3][2]);
            acc[0][3] = fmaf(av0, bq.w, acc[0][3]);
            acc[1][3] = fmaf(av1, bq.w, acc[1][3]);
            acc[2][3] = fmaf(av2, bq.w, acc[2][3]);
            acc[3][3] = fmaf(av3, bq.w, acc[3][3]);
        }
        __syncthreads();
    }

    // Write to g_X[t][c][b]; rows tx*4..+3 stay within one timestep (4 | 32)
    const int t  = blockIdx.x * 2 + (tx >> 3);
    const int bb = (tx & 7) * 4;
#pragma unroll
    for (int ci = 0; ci < 4; ci++) {
        const int c = n0 + ty * 4 + ci;
        const float bv = bias[c];
        float4 v = make_float4(acc[0][ci] + bv, acc[1][ci] + bv,
                               acc[2][ci] + bv, acc[3][ci] + bv);
        *(float4*)&g_X[((size_t)t * N2 + c) * BATCH + bb] = v;
    }
}

// ---------------------------------------------------------------------------
// Persistent sequential scan for one layer.
// 64 blocks; block owns 4 h-columns (= 8 pre-columns: h_pre j, t_pre j+256).
// Per step: load full h (32KB) into smem, register-blocked dot with Whh slice
// held in registers (4 cols x 16 k per thread, 16-way K-split), shuffle+smem
// reduce, gates, write own h cols + out row slice, grid barrier.
// ---------------------------------------------------------------------------
__global__ __launch_bounds__(256, 1) void scan_kernel(
    const float* __restrict__ Whh,          // [256, 768]
    const int* __restrict__ length,         // [32]  (JAX x64 disabled -> int32!)
    float* __restrict__ out_opt,            // null -> g_out0 (layer 0); else d_out
    float* __restrict__ hn_out)             // [32*256] final hidden for this layer
{
    __shared__ __align__(16) float hs[HID * BATCH];  // h, layout [k][r]
    __shared__ float red[8][8][33];                  // ks-pair partials
    __shared__ float pre_s[8][33];                   // reduced pre columns
    __shared__ __align__(16) float out_s[BATCH][4];  // staged output slice

    float* outp = out_opt ? out_opt : g_out0;
    const int tid   = threadIdx.x;
    const int jbase = blockIdx.x * 4;
    // dot-phase decomposition: 8 row-groups x 2 col-groups x 16 k-slices
    const int rg = tid & 7;
    const int cg = (tid >> 3) & 1;
    const int ks = tid >> 4;
    // gate-phase decomposition
    const int gr = tid & 31;
    const int gp = tid >> 5;
    const int len_r = length[gr];

    // Whh slice in registers: 4 cols x 16 k values (reused 2048 times)
    float w[4][16];
    {
        const int colbase = jbase + (cg ? HID : 0);
#pragma unroll
        for (int ci = 0; ci < 4; ci++)
#pragma unroll
            for (int kk = 0; kk < 16; kk++)
                w[ci][kk] = Whh[(size_t)(ks * 16 + kk) * G3 + colbase + ci];
    }

    // h0 = 0: zero our own columns
    if (tid < 128) {
        g_h[0][(jbase + (tid >> 5)) * BATCH + (tid & 31)] = 0.f;
    }
    grid_barrier(SCAN_BLOCKS);

    int cur = 0;
    for (int t = 0; t < T_LEN; t++) {
        // Broadcast h into smem (L2 reads; L1 is stale across SMs)
        {
            const float4* src = (const float4*)g_h[cur];
            float4* dst = (float4*)hs;
#pragma unroll
            for (int i = tid; i < (HID * BATCH / 4); i += 256)
                dst[i] = __ldcg(src + i);
        }
        __syncthreads();

        // Partial dot: acc[ri][ci] over this thread's 16-k slice
        float acc[4][4];
#pragma unroll
        for (int i = 0; i < 4; i++)
#pragma unroll
            for (int j = 0; j < 4; j++) acc[i][j] = 0.f;

        const int kb = ks * 16;
#pragma unroll
        for (int kk = 0; kk < 16; kk++) {
            const float4 hv = *(const float4*)&hs[(kb + kk) * BATCH + rg * 4];
#pragma unroll
            for (int ci = 0; ci < 4; ci++) {
                const float wv = w[ci][kk];
                acc[0][ci] = fmaf(hv.x, wv, acc[0][ci]);
                acc[1][ci] = fmaf(hv.y, wv, acc[1][ci]);
                acc[2][ci] = fmaf(hv.z, wv, acc[2][ci]);
                acc[3][ci] = fmaf(hv.w, wv, acc[3][ci]);
            }
        }

        // Combine adjacent k-slices (lane ^ 16 flips ks bit 0, same warp)
#pragma unroll
        for (int ri = 0; ri < 4; ri++)
#pragma unroll
            for (int ci = 0; ci < 4; ci++)
                acc[ri][ci] += __shfl_xor_sync(0xffffffffu, acc[ri][ci], 16);
        if ((ks & 1) == 0) {
#pragma unroll
            for (int ci = 0; ci < 4; ci++)
#pragma unroll
                for (int ri = 0; ri < 4; ri++)
                    red[ks >> 1][cg * 4 + ci][rg * 4 + ri] = acc[ri][ci];
        }
        __syncthreads();

        // Final reduce: thread (gr, gp) sums 8 partials
        {
            float s = 0.f;
#pragma unroll
            for (int i = 0; i < 8; i++) s += red[i][gp][gr];
            pre_s[gp][gr] = s;
        }
        __syncthreads();

        // Gates (128 threads: one per (row, local h-col))
        if (gp < 4) {
            const int j = jbase + gp;
            const float hp = pre_s[gp][gr]     + g_X[((size_t)t * N2 + j) * BATCH + gr];
            const float tp = pre_s[gp + 4][gr] + g_X[((size_t)t * N2 + HID + j) * BATCH + gr];
            const float hprev = hs[j * BATCH + gr];
            const float tg    = 1.f / (1.f + __expf(-tp));
            const float cgate = 1.f / (1.f + __expf(-tg));   // bug-faithful sigmoid(sigmoid)
            const float st    = tanhf(hp) * tg + hprev * cgate;
            const float hnew  = (t < len_r) ? st : hprev;
            g_h[cur ^ 1][j * BATCH + gr] = hnew;
            out_s[gr][gp] = hnew;
        }
        __syncthreads();

        // Coalesced output write: out[t][r][jbase..jbase+3]
        if (tid < 32) {
            const float4 v = *(const float4*)&out_s[tid][0];
            *(float4*)&outp[((size_t)t * BATCH + tid) * HID + jbase] = v;
        }

        cur ^= 1;
        grid_barrier(SCAN_BLOCKS);
    }

    // Final hidden state for this layer
    if (tid < 128) {
        const int jl = tid >> 5, r = tid & 31;
        hn_out[r * HID + jbase + jl] = g_h[cur][(jbase + jl) * BATCH + r];
    }
}

// ---------------------------------------------------------------------------
// Launch: gemm0 -> scan0 -> gemm1 -> scan1 (all graph-capturable)
// ---------------------------------------------------------------------------
extern "C" void kernel_launch(void* const* d_in, const int* in_sizes, int n_in,
                              void* d_out, int out_size) {
    const float* input  = (const float*)d_in[0];
    const int*   length = (const int*)d_in[1];
    const float* Wih0   = (const float*)d_in[2];
    const float* Whh0   = (const float*)d_in[3];
    const float* b0     = (const float*)d_in[4];
    const float* Wih1   = (const float*)d_in[5];
    const float* Whh1   = (const float*)d_in[6];
    const float* b1     = (const float*)d_in[7];

    float* out1 = (float*)d_out;                                  // [T,B,H]
    float* hn   = (float*)d_out + (size_t)T_LEN * BATCH * HID;    // [2,B,H]

    dim3 ggrid((T_LEN * BATCH) / 64, N2 / 64);

    gemm_x_kernel<<<ggrid, 256>>>(input, Wih0, b0);
    scan_kernel<<<SCAN_BLOCKS, 256>>>(Whh0, length, nullptr, hn);
    gemm_x_kernel<<<ggrid, 256>>>(nullptr, Wih1, b1);
    scan_kernel<<<SCAN_BLOCKS, 256>>>(Whh1, length, out1, hn + BATCH * HID);
}

// round 4
// speedup vs baseline: 1.6292x; 1.6292x over previous
#include <cuda_runtime.h>

// Problem constants
#define T_LEN 2048
#define BATCH 32
#define DIM   256
#define HID   256
#define G3    768   // 3H (weight leading dim)
#define N2    512   // only first 2H columns matter (c_pre is dead)
#define NBLK  128   // 64 layer-0 blocks + 64 layer-1 blocks (co-resident, <=148 SMs)

// ---------------------------------------------------------------------------
// Device scratch
// ---------------------------------------------------------------------------
__device__ float g_X[(size_t)T_LEN * N2 * BATCH];   // x@Wih0 + b0, layout [t][c(512)][b(32)]
__device__ float g_h0[2][HID * BATCH];              // layer-0 hidden, [k][r]
__device__ float g_h1[2][HID * BATCH];              // layer-1 hidden, [k][r]
__device__ unsigned g_flag[NBLK * 8];               // padded progress flags (32B apart)

// ---------------------------------------------------------------------------
// Reset: zero flags + initial hidden states (runs every replay)
// ---------------------------------------------------------------------------
__global__ void reset_kernel() {
    int tid = blockIdx.x * blockDim.x + threadIdx.x;
    if (tid < NBLK * 8) g_flag[tid] = 0u;
    for (int i = tid; i < HID * BATCH; i += gridDim.x * blockDim.x) {
        g_h0[0][i] = 0.f;
        g_h1[0][i] = 0.f;
    }
}

// ---------------------------------------------------------------------------
// GEMM: g_X = input @ Wih0[:, :512] + b0[:512]   (layer-0 x-term only)
// input: [65536, 256] row-major. Output layout [t][c][b].
// ---------------------------------------------------------------------------
__global__ __launch_bounds__(256, 1) void gemm_x_kernel(
    const float* __restrict__ A,
    const float* __restrict__ W,
    const float* __restrict__ bias)
{
    __shared__ float As[32][65];
    __shared__ float Bs[32][64];

    const int tid = threadIdx.x;
    const int m0  = blockIdx.x * 64;
    const int n0  = blockIdx.y * 64;
    const int tx  = tid & 15;
    const int ty  = tid >> 4;
    const int ar  = tid >> 2;
    const int ak  = (tid & 3) * 8;
    const int bk  = tid >> 3;
    const int bc  = (tid & 7) * 8;

    float acc[4][4];
#pragma unroll
    for (int i = 0; i < 4; i++)
#pragma unroll
        for (int j = 0; j < 4; j++) acc[i][j] = 0.f;

    for (int k0 = 0; k0 < DIM; k0 += 32) {
        float4 a0  = *(const float4*)&A[(size_t)(m0 + ar) * DIM + k0 + ak];
        float4 a1  = *(const float4*)&A[(size_t)(m0 + ar) * DIM + k0 + ak + 4];
        float4 b0v = *(const float4*)&W[(size_t)(k0 + bk) * G3 + n0 + bc];
        float4 b1v = *(const float4*)&W[(size_t)(k0 + bk) * G3 + n0 + bc + 4];

        As[ak + 0][ar] = a0.x; As[ak + 1][ar] = a0.y;
        As[ak + 2][ar] = a0.z; As[ak + 3][ar] = a0.w;
        As[ak + 4][ar] = a1.x; As[ak + 5][ar] = a1.y;
        As[ak + 6][ar] = a1.z; As[ak + 7][ar] = a1.w;
        *(float4*)&Bs[bk][bc]     = b0v;
        *(float4*)&Bs[bk][bc + 4] = b1v;
        __syncthreads();

#pragma unroll
        for (int kk = 0; kk < 32; kk++) {
            const float av0 = As[kk][tx * 4 + 0];
            const float av1 = As[kk][tx * 4 + 1];
            const float av2 = As[kk][tx * 4 + 2];
            const float av3 = As[kk][tx * 4 + 3];
            const float4 bq = *(const float4*)&Bs[kk][ty * 4];
            acc[0][0] = fmaf(av0, bq.x, acc[0][0]);
            acc[1][0] = fmaf(av1, bq.x, acc[1][0]);
            acc[2][0] = fmaf(av2, bq.x, acc[2][0]);
            acc[3][0] = fmaf(av3, bq.x, acc[3][0]);
            acc[0][1] = fmaf(av0, bq.y, acc[0][1]);
            acc[1][1] = fmaf(av1, bq.y, acc[1][1]);
            acc[2][1] = fmaf(av2, bq.y, acc[2][1]);
            acc[3][1] = fmaf(av3, bq.y, acc[3][1]);
            acc[0][2] = fmaf(av0, bq.z, acc[0][2]);
            acc[1][2] = fmaf(av1, bq.z, acc[1][2]);
            acc[2][2] = fmaf(av2, bq.z, acc[2][2]);
            acc[3][2] = fmaf(av3, bq.z, acc[3][2]);
            acc[0][3] = fmaf(av0, bq.w, acc[0][3]);
            acc[1][3] = fmaf(av1, bq.w, acc[1][3]);
            acc[2][3] = fmaf(av2, bq.w, acc[2][3]);
            acc[3][3] = fmaf(av3, bq.w, acc[3][3]);
        }
        __syncthreads();
    }

    const int t  = blockIdx.x * 2 + (tx >> 3);
    const int bb = (tx & 7) * 4;
#pragma unroll
    for (int ci = 0; ci < 4; ci++) {
        const int c = n0 + ty * 4 + ci;
        const float bv = bias[c];
        float4 v = make_float4(acc[0][ci] + bv, acc[1][ci] + bv,
                               acc[2][ci] + bv, acc[3][ci] + bv);
        *(float4*)&g_X[((size_t)t * N2 + c) * BATCH + bb] = v;
    }
}

// ---------------------------------------------------------------------------
// Fused dual-layer persistent scan.
// Blocks 0..63  : layer 0, own 4 h-cols, K=256 dot vs Whh0 (+ g_X x-term).
// Blocks 64..127: layer 1 (lags 1 step), K=512 dot vs [Whh1 ; Wih1] over
//                 [h1 ; h0_lagged]; x-term computed on the fly.
// Decomposition: 256 thr = RG(4: 8 rows) x CG(2: 4 cols) x KS(32: 16 k).
// Smem hs uses a XOR-by-(k>>4) chunk swizzle -> 2-way-max bank conflicts.
// Distributed flag barrier: release-store flag[bid]=i+1; acquire-poll all.
// ---------------------------------------------------------------------------
__global__ __launch_bounds__(256, 1) void fused_scan(
    const float* __restrict__ Whh0,   // [256,768]
    const float* __restrict__ Whh1,   // [256,768]
    const float* __restrict__ Wih1,   // [256,768]
    const float* __restrict__ b1,     // [768]
    const int*   __restrict__ length, // [32] int32
    float* __restrict__ out1,         // [T,B,H]
    float* __restrict__ hn)           // [2,B,H]
{
    extern __shared__ float smem[];
    float* hs    = smem;                          // 512*32 floats (swizzled)
    float* red   = smem + N2 * BATCH;             // [8 warps][8 cols][33]
    float* pre_s = red + 8 * 8 * 33;              // [8][33]
    float* out_s = pre_s + 8 * 33;                // [32][4]
    float4* hs4  = (float4*)hs;

    const int tid   = threadIdx.x;
    const int bid   = blockIdx.x;
    const int layer = bid >> 6;
    const int jb    = (bid & 63) * 4;

    const int rg   = tid & 3;          // row group: rows rg*8..rg*8+7
    const int cg   = (tid >> 2) & 1;   // col half: h_pre vs t_pre
    const int ks   = tid >> 3;         // k slice: k = ks*16..ks*16+15
    const int warp = tid >> 5;
    const int gr   = tid & 31;         // gate row (batch)
    const int gp   = tid >> 5;         // gate col (0..7)
    const int colbase = jb + cg * HID;
    const int swz  = ks & 3;           // = (k>>4)&3 for this thread's k's

    const int len_r = length[gr];

    // ---- weights in registers: 4 cols x 16 k ----
    float w[4][16];
    if (layer == 0) {
        if (ks < 16) {
#pragma unroll
            for (int ci = 0; ci < 4; ci++)
#pragma unroll
                for (int kk = 0; kk < 16; kk++)
                    w[ci][kk] = Whh0[(size_t)(ks * 16 + kk) * G3 + colbase + ci];
        } else {
#pragma unroll
            for (int ci = 0; ci < 4; ci++)
#pragma unroll
                for (int kk = 0; kk < 16; kk++) w[ci][kk] = 0.f;
        }
    } else {
        const float* W = (ks < 16) ? Whh1 : Wih1;
        const int kb0 = (ks & 15) * 16;
#pragma unroll
        for (int ci = 0; ci < 4; ci++)
#pragma unroll
            for (int kk = 0; kk < 16; kk++)
                w[ci][kk] = W[(size_t)(kb0 + kk) * G3 + colbase + ci];
    }

    // bias for layer 1 gates
    float bh = 0.f, bt = 0.f;
    if (layer && gp < 4) {
        bh = b1[jb + gp];
        bt = b1[HID + jb + gp];
    }

    // layer-0: zero the upper (unused) half of hs once; k>=256 contributes 0
    if (!layer) {
        for (int i = tid; i < HID * BATCH; i += 256) hs[HID * BATCH + i] = 0.f;
    }

    for (int i = 0; i <= T_LEN; i++) {
        const int  t   = layer ? (i - 1) : i;
        const bool act = layer ? (i >= 1) : (i < T_LEN);

        // ---- wait: all flags >= i ----
        if (i > 0) {
            if (tid < NBLK) {
                unsigned v;
                do {
                    asm volatile("ld.acquire.gpu.global.u32 %0, [%1];"
                                 : "=r"(v) : "l"(&g_flag[tid * 8]) : "memory");
                } while (v < (unsigned)i);
            }
        }
        __syncthreads();

        float xh = 0.f, xt = 0.f;
        if (act) {
            // prefetch layer-0 x-term (DRAM latency hidden behind the dot)
            if (!layer && gp < 4) {
                const size_t bo = ((size_t)t * N2 + jb + gp) * BATCH + gr;
                xh = __ldg(&g_X[bo]);
                xt = __ldg(&g_X[bo + (size_t)HID * BATCH]);
            }

            // ---- stage h into swizzled smem (L2 reads; L1 stale across SMs) ----
            {
                const float4* srcA = (const float4*)(layer ? g_h1[(i + 1) & 1]
                                                           : g_h0[i & 1]);
                for (int idx = tid; idx < 2048; idx += 256) {
                    const int k = idx >> 3, c = idx & 7;
                    hs4[k * 8 + (c ^ ((k >> 4) & 3))] = __ldcg(srcA + idx);
                }
                if (layer) {
                    const float4* srcX = (const float4*)g_h0[i & 1];
                    for (int idx = tid; idx < 2048; idx += 256) {
                        const int k = 256 + (idx >> 3), c = idx & 7;
                        hs4[k * 8 + (c ^ ((k >> 4) & 3))] = __ldcg(srcX + idx);
                    }
                }
            }
            __syncthreads();

            // ---- dot: acc[ci][ri] over this thread's 16-k slice, 8 rows ----
            float acc[4][8];
#pragma unroll
            for (int ci = 0; ci < 4; ci++)
#pragma unroll
                for (int ri = 0; ri < 8; ri++) acc[ci][ri] = 0.f;

            const int kb = ks * 16;
#pragma unroll
            for (int kk = 0; kk < 16; kk++) {
                const int base4 = (kb + kk) * 8;
                const float4 ha = hs4[base4 + ((rg * 2)     ^ swz)];
                const float4 hb = hs4[base4 + ((rg * 2 + 1) ^ swz)];
#pragma unroll
                for (int ci = 0; ci < 4; ci++) {
                    const float wv = w[ci][kk];
                    acc[ci][0] = fmaf(ha.x, wv, acc[ci][0]);
                    acc[ci][1] = fmaf(ha.y, wv, acc[ci][1]);
                    acc[ci][2] = fmaf(ha.z, wv, acc[ci][2]);
                    acc[ci][3] = fmaf(ha.w, wv, acc[ci][3]);
                    acc[ci][4] = fmaf(hb.x, wv, acc[ci][4]);
                    acc[ci][5] = fmaf(hb.y, wv, acc[ci][5]);
                    acc[ci][6] = fmaf(hb.z, wv, acc[ci][6]);
                    acc[ci][7] = fmaf(hb.w, wv, acc[ci][7]);
                }
            }

            // combine 4 k-slices within warp (tid bits 3,4 = ks bits 0,1)
#pragma unroll
            for (int ci = 0; ci < 4; ci++)
#pragma unroll
                for (int ri = 0; ri < 8; ri++) {
                    float v = acc[ci][ri];
                    v += __shfl_xor_sync(0xffffffffu, v, 8);
                    v += __shfl_xor_sync(0xffffffffu, v, 16);
                    acc[ci][ri] = v;
                }
            if ((tid & 24) == 0) {     // lanes 0..7: all (rg,cg) combos
#pragma unroll
                for (int ci = 0; ci < 4; ci++)
#pragma unroll
                    for (int ri = 0; ri < 8; ri++)
                        red[(warp * 8 + cg * 4 + ci) * 33 + rg * 8 + ri] = acc[ci][ri];
            }
            __syncthreads();

            // final reduce across 8 warps
            {
                float s = 0.f;
#pragma unroll
                for (int wp = 0; wp < 8; wp++) s += red[(wp * 8 + gp) * 33 + gr];
                pre_s[gp * 33 + gr] = s;
            }
            __syncthreads();

            // ---- gates ----
            if (gp < 4) {
                const int j = jb + gp;
                const float ph = pre_s[gp * 33 + gr]       + (layer ? bh : xh);
                const float pt = pre_s[(gp + 4) * 33 + gr] + (layer ? bt : xt);
                // swizzled read of h_prev
                const float hprev = hs[j * 32 + ((((unsigned)gr >> 2) ^ ((j >> 4) & 3)) << 2) + (gr & 3)];
                const float tg    = 1.f / (1.f + __expf(-pt));
                const float cgate = 1.f / (1.f + __expf(-tg));  // bug-faithful
                const float st    = tanhf(ph) * tg + hprev * cgate;
                const float hnew  = (t < len_r) ? st : hprev;
                if (layer) {
                    g_h1[i & 1][j * BATCH + gr] = hnew;
                    out_s[gr * 4 + gp] = hnew;
                    if (t == T_LEN - 1) hn[BATCH * HID + gr * HID + j] = hnew;
                } else {
                    g_h0[(i + 1) & 1][j * BATCH + gr] = hnew;
                    if (t == T_LEN - 1) hn[gr * HID + j] = hnew;
                }
            }
        }

        // ---- publish progress (all blocks, every iteration) ----
        __threadfence();
        __syncthreads();
        if (tid == 0) {
            asm volatile("st.release.gpu.global.u32 [%0], %1;"
                         :: "l"(&g_flag[bid * 8]), "r"((unsigned)(i + 1)) : "memory");
        }

        // output write off the critical path (after publish)
        if (layer && act && tid < 32) {
            const float4 v = *(const float4*)&out_s[tid * 4];
            *(float4*)&out1[((size_t)t * BATCH + tid) * HID + jb] = v;
        }
    }
}

// ---------------------------------------------------------------------------
// Launch: reset -> gemm (layer-0 x-term) -> fused dual-layer scan
// ---------------------------------------------------------------------------
extern "C" void kernel_launch(void* const* d_in, const int* in_sizes, int n_in,
                              void* d_out, int out_size) {
    const float* input  = (const float*)d_in[0];
    const int*   length = (const int*)d_in[1];
    const float* Wih0   = (const float*)d_in[2];
    const float* Whh0   = (const float*)d_in[3];
    const float* b0     = (const float*)d_in[4];
    const float* Wih1   = (const float*)d_in[5];
    const float* Whh1   = (const float*)d_in[6];
    const float* b1     = (const float*)d_in[7];

    float* out1 = (float*)d_out;
    float* hn   = (float*)d_out + (size_t)T_LEN * BATCH * HID;

    const int smem_bytes = (N2 * BATCH + 8 * 8 * 33 + 8 * 33 + 32 * 4) * 4;
    cudaFuncSetAttribute(fused_scan, cudaFuncAttributeMaxDynamicSharedMemorySize,
                         smem_bytes);

    reset_kernel<<<8, 256>>>();
    gemm_x_kernel<<<dim3((T_LEN * BATCH) / 64, N2 / 64), 256>>>(input, Wih0, b0);
    fused_scan<<<NBLK, 256, smem_bytes>>>(Whh0, Whh1, Wih1, b1, length, out1, hn);
}

// round 5
// speedup vs baseline: 1.6819x; 1.0323x over previous
#include <cuda_runtime.h>
#include <cstdint>

// Problem constants
#define T_LEN 2048
#define BATCH 32
#define DIM   256
#define HID   256
#define G3    768   // 3H (weight leading dim)
#define N2    512   // only first 2H columns matter (c_pre is dead)
#define NBLK  128   // 64 layer-0 blocks + 64 layer-1 blocks (co-resident)

// ---------------------------------------------------------------------------
// Device scratch
// ---------------------------------------------------------------------------
__device__ float g_X[(size_t)T_LEN * N2 * BATCH];   // x@Wih0 + b0, [t][c(512)][b(32)]
__device__ float g_h0[4][HID * BATCH];              // layer-0 hidden ring (state s in slot s&3)
__device__ float g_h1[2][HID * BATCH];              // layer-1 hidden (state s in slot s&1)
__device__ unsigned g_flag[NBLK * 8];               // padded progress flags (32B apart)

// ---------------------------------------------------------------------------
__global__ void reset_kernel() {
    int tid = blockIdx.x * blockDim.x + threadIdx.x;
    if (tid < NBLK * 8) g_flag[tid] = 0u;
    for (int i = tid; i < HID * BATCH; i += gridDim.x * blockDim.x) {
        g_h0[0][i] = 0.f;
        g_h1[0][i] = 0.f;
    }
}

// ---------------------------------------------------------------------------
// GEMM: g_X = input @ Wih0[:, :512] + b0[:512]
// ---------------------------------------------------------------------------
__global__ __launch_bounds__(256, 1) void gemm_x_kernel(
    const float* __restrict__ A,
    const float* __restrict__ W,
    const float* __restrict__ bias)
{
    __shared__ float As[32][65];
    __shared__ float Bs[32][64];

    const int tid = threadIdx.x;
    const int m0  = blockIdx.x * 64;
    const int n0  = blockIdx.y * 64;
    const int tx  = tid & 15;
    const int ty  = tid >> 4;
    const int ar  = tid >> 2;
    const int ak  = (tid & 3) * 8;
    const int bk  = tid >> 3;
    const int bc  = (tid & 7) * 8;

    float acc[4][4];
#pragma unroll
    for (int i = 0; i < 4; i++)
#pragma unroll
        for (int j = 0; j < 4; j++) acc[i][j] = 0.f;

    for (int k0 = 0; k0 < DIM; k0 += 32) {
        float4 a0  = *(const float4*)&A[(size_t)(m0 + ar) * DIM + k0 + ak];
        float4 a1  = *(const float4*)&A[(size_t)(m0 + ar) * DIM + k0 + ak + 4];
        float4 b0v = *(const float4*)&W[(size_t)(k0 + bk) * G3 + n0 + bc];
        float4 b1v = *(const float4*)&W[(size_t)(k0 + bk) * G3 + n0 + bc + 4];

        As[ak + 0][ar] = a0.x; As[ak + 1][ar] = a0.y;
        As[ak + 2][ar] = a0.z; As[ak + 3][ar] = a0.w;
        As[ak + 4][ar] = a1.x; As[ak + 5][ar] = a1.y;
        As[ak + 6][ar] = a1.z; As[ak + 7][ar] = a1.w;
        *(float4*)&Bs[bk][bc]     = b0v;
        *(float4*)&Bs[bk][bc + 4] = b1v;
        __syncthreads();

#pragma unroll
        for (int kk = 0; kk < 32; kk++) {
            const float av0 = As[kk][tx * 4 + 0];
            const float av1 = As[kk][tx * 4 + 1];
            const float av2 = As[kk][tx * 4 + 2];
            const float av3 = As[kk][tx * 4 + 3];
            const float4 bq = *(const float4*)&Bs[kk][ty * 4];
            acc[0][0] = fmaf(av0, bq.x, acc[0][0]);
            acc[1][0] = fmaf(av1, bq.x, acc[1][0]);
            acc[2][0] = fmaf(av2, bq.x, acc[2][0]);
            acc[3][0] = fmaf(av3, bq.x, acc[3][0]);
            acc[0][1] = fmaf(av0, bq.y, acc[0][1]);
            acc[1][1] = fmaf(av1, bq.y, acc[1][1]);
            acc[2][1] = fmaf(av2, bq.y, acc[2][1]);
            acc[3][1] = fmaf(av3, bq.y, acc[3][1]);
            acc[0][2] = fmaf(av0, bq.z, acc[0][2]);
            acc[1][2] = fmaf(av1, bq.z, acc[1][2]);
            acc[2][2] = fmaf(av2, bq.z, acc[2][2]);
            acc[3][2] = fmaf(av3, bq.z, acc[3][2]);
            acc[0][3] = fmaf(av0, bq.w, acc[0][3]);
            acc[1][3] = fmaf(av1, bq.w, acc[1][3]);
            acc[2][3] = fmaf(av2, bq.w, acc[2][3]);
            acc[3][3] = fmaf(av3, bq.w, acc[3][3]);
        }
        __syncthreads();
    }

    const int t  = blockIdx.x * 2 + (tx >> 3);
    const int bb = (tx & 7) * 4;
#pragma unroll
    for (int ci = 0; ci < 4; ci++) {
        const int c = n0 + ty * 4 + ci;
        const float bv = bias[c];
        float4 v = make_float4(acc[0][ci] + bv, acc[1][ci] + bv,
                               acc[2][ci] + bv, acc[3][ci] + bv);
        *(float4*)&g_X[((size_t)t * N2 + c) * BATCH + bb] = v;
    }
}

// ---------------------------------------------------------------------------
// Packed f32x2 helpers (sm_103a: FFMA2 only reachable via PTX)
// ---------------------------------------------------------------------------
__device__ __forceinline__ unsigned long long pack2(float v) {
    unsigned long long r;
    asm("mov.b64 %0, {%1, %1};" : "=l"(r) : "f"(v));
    return r;
}
__device__ __forceinline__ void fma2(unsigned long long& d,
                                     unsigned long long a, unsigned long long b) {
    asm("fma.rn.f32x2 %0, %1, %2, %0;" : "+l"(d) : "l"(a), "l"(b));
}
__device__ __forceinline__ unsigned long long add2(unsigned long long a,
                                                   unsigned long long b) {
    unsigned long long r;
    asm("add.rn.f32x2 %0, %1, %2;" : "=l"(r) : "l"(a), "l"(b));
    return r;
}

// Dot over this thread's KN-long k-slice; acc[ci][p] = packed row-pairs.
template <int KN>
__device__ __forceinline__ void dot_slice(
    const ulonglong2* __restrict__ hsU, const float (&w)[4][16],
    int kb, int rg, int swz, unsigned long long (&acc)[4][4])
{
#pragma unroll
    for (int kk = 0; kk < KN; kk++) {
        const int base4 = (kb + kk) * 8;
        const ulonglong2 ha = hsU[base4 + ((rg * 2)     ^ swz)];  // rows rg*8+0..3
        const ulonglong2 hb = hsU[base4 + ((rg * 2 + 1) ^ swz)];  // rows rg*8+4..7
#pragma unroll
        for (int ci = 0; ci < 4; ci++) {
            const unsigned long long w2 = pack2(w[ci][kk]);
            fma2(acc[ci][0], ha.x, w2);
            fma2(acc[ci][1], ha.y, w2);
            fma2(acc[ci][2], hb.x, w2);
            fma2(acc[ci][3], hb.y, w2);
        }
    }
}

// ---------------------------------------------------------------------------
// Fused dual-layer persistent scan.
// Blocks 0..63  : layer 0, K=256 dot (32 slices x 8 k) + g_X x-term.
// Blocks 64..127: layer 1 (lags 1 step), K=512 over [h1 ; h0_lagged].
// h0 is a 4-deep ring so layer 0 runs ahead; layer 0 waits L0 flags>=i and
// L1 flags>=i-2 (ring safety); layer 1 waits all flags>=i.
// ---------------------------------------------------------------------------
__global__ __launch_bounds__(256, 1) void fused_scan(
    const float* __restrict__ Whh0,   // [256,768]
    const float* __restrict__ Whh1,   // [256,768]
    const float* __restrict__ Wih1,   // [256,768]
    const float* __restrict__ b1,     // [768]
    const int*   __restrict__ length, // [32] int32
    float* __restrict__ out1,         // [T,B,H]
    float* __restrict__ hn)           // [2,B,H]
{
    extern __shared__ float smem[];
    float* hs    = smem;                    // 512*32 floats (chunk-swizzled)
    float* red   = smem + N2 * BATCH;       // [8 warps * 8 cols][34]
    float* out_s = red + 64 * 34;           // [32][4]
    float4*     hs4 = (float4*)hs;
    const ulonglong2* hsU = (const ulonglong2*)hs;

    const int tid   = threadIdx.x;
    const int bid   = blockIdx.x;
    const int layer = bid >> 6;
    const int jb    = (bid & 63) * 4;

    const int rg   = tid & 3;              // row group (8 batch rows)
    const int cg   = (tid >> 2) & 1;       // col half: h_pre vs t_pre
    const int ks   = tid >> 3;             // k slice index (32 slices)
    const int warp = tid >> 5;
    const int gr   = tid & 31;             // gate batch row
    const int gp   = tid >> 5;             // gate col (warp id)
    const int colbase = jb + cg * HID;
    const int swz  = layer ? (ks & 3) : ((ks >> 1) & 3);  // = (k>>4)&3 for slice

    const int len_r = length[gr];

    // ---- weights in registers ----
    float w[4][16];
    if (layer == 0) {
        // 32 slices x 8 k covering K=256
#pragma unroll
        for (int ci = 0; ci < 4; ci++)
#pragma unroll
            for (int kk = 0; kk < 8; kk++)
                w[ci][kk] = Whh0[(size_t)(ks * 8 + kk) * G3 + colbase + ci];
#pragma unroll
        for (int ci = 0; ci < 4; ci++)
#pragma unroll
            for (int kk = 8; kk < 16; kk++) w[ci][kk] = 0.f;
    } else {
        // 32 slices x 16 k covering K=512: [Whh1 ; Wih1]
        const float* W = (ks < 16) ? Whh1 : Wih1;
        const int kb0 = (ks & 15) * 16;
#pragma unroll
        for (int ci = 0; ci < 4; ci++)
#pragma unroll
            for (int kk = 0; kk < 16; kk++)
                w[ci][kk] = W[(size_t)(kb0 + kk) * G3 + colbase + ci];
    }

    float bh = 0.f, bt = 0.f;
    if (layer && gp < 4) {
        bh = b1[jb + gp];
        bt = b1[HID + jb + gp];
    }

    const int imax = layer ? T_LEN : (T_LEN - 1);

    for (int i = 0; i <= imax; i++) {
        const int  t   = layer ? (i - 1) : i;
        const bool act = layer ? (i >= 1) : true;

        // ---- wait on progress flags ----
        if (i > 0) {
            if (tid < NBLK) {
                const int target = (layer || tid < 64) ? i : (i - 2);
                if (target > 0) {
                    unsigned v;
                    do {
                        asm volatile("ld.acquire.gpu.global.u32 %0, [%1];"
                                     : "=r"(v) : "l"(&g_flag[tid * 8]) : "memory");
                    } while (v < (unsigned)target);
                }
            }
            __syncthreads();
        }

        if (act) {
            // prefetch layer-0 x-term (DRAM latency hides behind staging+dot)
            float xh = 0.f, xt = 0.f;
            if (!layer && gp < 4) {
                const size_t bo = ((size_t)t * N2 + jb + gp) * BATCH + gr;
                xh = __ldg(&g_X[bo]);
                xt = __ldg(&g_X[bo + (size_t)HID * BATCH]);
            }

            // ---- stage h into swizzled smem (L2 reads; L1 stale across SMs) ----
            {
                const float4* srcA = (const float4*)(layer ? g_h1[(i + 1) & 1]
                                                           : g_h0[i & 3]);
                for (int idx = tid; idx < 2048; idx += 256) {
                    const int k = idx >> 3, c = idx & 7;
                    hs4[k * 8 + (c ^ ((k >> 4) & 3))] = __ldcg(srcA + idx);
                }
                if (layer) {
                    const float4* srcX = (const float4*)g_h0[i & 3];
                    for (int idx = tid; idx < 2048; idx += 256) {
                        const int k = 256 + (idx >> 3), c = idx & 7;
                        hs4[k * 8 + (c ^ ((k >> 4) & 3))] = __ldcg(srcX + idx);
                    }
                }
            }
            __syncthreads();

            // ---- packed dot ----
            unsigned long long acc[4][4];
#pragma unroll
            for (int ci = 0; ci < 4; ci++)
#pragma unroll
                for (int p = 0; p < 4; p++) acc[ci][p] = 0ull;

            if (layer) dot_slice<16>(hsU, w, ks * 16, rg, swz, acc);
            else       dot_slice<8>(hsU, w, ks * 8,  rg, swz, acc);

            // combine 4 k-slices within warp (tid bits 3,4 = ks bits 0,1)
#pragma unroll
            for (int ci = 0; ci < 4; ci++)
#pragma unroll
                for (int p = 0; p < 4; p++) {
                    unsigned long long v = acc[ci][p];
                    v = add2(v, __shfl_xor_sync(0xffffffffu, v, 8));
                    v = add2(v, __shfl_xor_sync(0xffffffffu, v, 16));
                    acc[ci][p] = v;
                }
            if ((tid & 24) == 0) {  // lanes 0..7: all (rg,cg) combos
#pragma unroll
                for (int ci = 0; ci < 4; ci++)
#pragma unroll
                    for (int p = 0; p < 4; p++)
                        *(unsigned long long*)&red[(warp * 8 + cg * 4 + ci) * 34
                                                   + rg * 8 + 2 * p] = acc[ci][p];
            }
            __syncthreads();

            // ---- final reduce fused with gates (warps 0-3 only) ----
            if (gp < 4) {
                float sh = 0.f, stt = 0.f;
#pragma unroll
                for (int wp = 0; wp < 8; wp++) {
                    sh  += red[(wp * 8 + gp)     * 34 + gr];
                    stt += red[(wp * 8 + gp + 4) * 34 + gr];
                }
                const int j = jb + gp;
                const float ph = sh  + (layer ? bh : xh);
                const float pt = stt + (layer ? bt : xt);
                const float hprev = hs[j * 32 +
                    ((((unsigned)gr >> 2) ^ ((j >> 4) & 3)) << 2) + (gr & 3)];
                const float tg    = 1.f / (1.f + __expf(-pt));
                const float cgate = 1.f / (1.f + __expf(-tg));   // bug-faithful
                const float st    = tanhf(ph) * tg + hprev * cgate;
                const float hnew  = (t < len_r) ? st : hprev;
                if (layer) {
                    g_h1[i & 1][j * BATCH + gr] = hnew;
                    out_s[gr * 4 + gp] = hnew;
                    if (t == T_LEN - 1) hn[BATCH * HID + gr * HID + j] = hnew;
                } else {
                    g_h0[(i + 1) & 3][j * BATCH + gr] = hnew;
                    if (t == T_LEN - 1) hn[gr * HID + j] = hnew;
                }
            }
        }

        // ---- publish progress: release store orders all prior writes ----
        __syncthreads();
        if (tid == 0) {
            asm volatile("st.release.gpu.global.u32 [%0], %1;"
                         :: "l"(&g_flag[bid * 8]), "r"((unsigned)(i + 1)) : "memory");
        }

        // output write off the critical path (after publish)
        if (layer && act && tid < 32) {
            const float4 v = *(const float4*)&out_s[tid * 4];
            *(float4*)&out1[((size_t)t * BATCH + tid) * HID + jb] = v;
        }
    }
}

// ---------------------------------------------------------------------------
extern "C" void kernel_launch(void* const* d_in, const int* in_sizes, int n_in,
                              void* d_out, int out_size) {
    const float* input  = (const float*)d_in[0];
    const int*   length = (const int*)d_in[1];
    const float* Wih0   = (const float*)d_in[2];
    const float* Whh0   = (const float*)d_in[3];
    const float* b0     = (const float*)d_in[4];
    const float* Wih1   = (const float*)d_in[5];
    const float* Whh1   = (const float*)d_in[6];
    const float* b1     = (const float*)d_in[7];

    float* out1 = (float*)d_out;
    float* hn   = (float*)d_out + (size_t)T_LEN * BATCH * HID;

    const int smem_bytes = (N2 * BATCH + 64 * 34 + 32 * 4) * 4;
    cudaFuncSetAttribute(fused_scan, cudaFuncAttributeMaxDynamicSharedMemorySize,
                         smem_bytes);

    reset_kernel<<<8, 256>>>();
    gemm_x_kernel<<<dim3((T_LEN * BATCH) / 64, N2 / 64), 256>>>(input, Wih0, b0);
    fused_scan<<<NBLK, 256, smem_bytes>>>(Whh0, Whh1, Wih1, b1, length, out1, hn);
}

// round 6
// speedup vs baseline: 1.8311x; 1.0887x over previous
#include <cuda_runtime.h>
#include <cstdint>

// Problem constants
#define T_LEN 2048
#define BATCH 32
#define DIM   256
#define HID   256
#define G3    768    // 3H (weight leading dim)
#define N2    512    // only first 2H columns matter (c_pre is dead)
#define NBLK  128    // 64 layer-0 + 64 layer-1 persistent scan blocks
#define NWORK 64     // gemm worker blocks
#define NTILE 8192   // 1024 bx (t-pairs) * 8 by (64-col tiles)

// ---------------------------------------------------------------------------
// Device scratch (allocations forbidden -> __device__ globals, zero-init)
// ---------------------------------------------------------------------------
__device__ float g_X[(size_t)T_LEN * N2 * BATCH];  // x@Wih0+b0, [t][c(512)][b(32)]
__device__ float g_h0[4][HID * BATCH];             // layer-0 hidden ring
__device__ float g_h1[2][HID * BATCH];             // layer-1 hidden
__device__ unsigned g_flag[NBLK * 8];              // monotonic progress flags
__device__ unsigned g_tcnt[T_LEN / 2];             // gemm tile counters (8/run each)
__device__ unsigned g_run;                         // completed-run counter

// ---------------------------------------------------------------------------
// Packed f32x2 helpers (FFMA2 only reachable via PTX on sm_103a)
// ---------------------------------------------------------------------------
__device__ __forceinline__ unsigned long long pack2(float v) {
    unsigned long long r;
    asm("mov.b64 %0, {%1, %1};" : "=l"(r) : "f"(v));
    return r;
}
__device__ __forceinline__ void fma2(unsigned long long& d,
                                     unsigned long long a, unsigned long long b) {
    asm("fma.rn.f32x2 %0, %1, %2, %0;" : "+l"(d) : "l"(a), "l"(b));
}
__device__ __forceinline__ unsigned long long add2(unsigned long long a,
                                                   unsigned long long b) {
    unsigned long long r;
    asm("add.rn.f32x2 %0, %1, %2;" : "=l"(r) : "l"(a), "l"(b));
    return r;
}

// Dot over this thread's KN-long k-slice; acc[ci][p] = packed batch-row pairs.
template <int KN>
__device__ __forceinline__ void dot_slice(
    const ulonglong2* __restrict__ hsU, const float (&w)[4][16],
    int kb, int rg, int swz, unsigned long long (&acc)[4][4])
{
#pragma unroll
    for (int kk = 0; kk < KN; kk++) {
        const int base4 = (kb + kk) * 8;
        const ulonglong2 ha = hsU[base4 + ((rg * 2)     ^ swz)];
        const ulonglong2 hb = hsU[base4 + ((rg * 2 + 1) ^ swz)];
#pragma unroll
        for (int ci = 0; ci < 4; ci++) {
            const unsigned long long w2 = pack2(w[ci][kk]);
            fma2(acc[ci][0], ha.x, w2);
            fma2(acc[ci][1], ha.y, w2);
            fma2(acc[ci][2], hb.x, w2);
            fma2(acc[ci][3], hb.y, w2);
        }
    }
}

// ---------------------------------------------------------------------------
// GEMM worker: grid-strided 64x64x256 tiles of g_X = input @ Wih0[:,:512]+b0.
// After each tile: fence + release-add the per-t-pair counter.
// ---------------------------------------------------------------------------
__device__ void gemm_worker(int wb, const float* __restrict__ A,
                            const float* __restrict__ W,
                            const float* __restrict__ bias, float* smem)
{
    float (*As)[65] = (float(*)[65])smem;
    float (*Bs)[64] = (float(*)[64])(smem + 32 * 65);

    const int tid = threadIdx.x;
    const int tx  = tid & 15;
    const int ty  = tid >> 4;
    const int ar  = tid >> 2;
    const int ak  = (tid & 3) * 8;
    const int bk  = tid >> 3;
    const int bc  = (tid & 7) * 8;

    for (int n = wb; n < NTILE; n += NWORK) {
        const int bx = n >> 3;
        const int m0 = bx * 64;
        const int n0 = (n & 7) * 64;

        float acc[4][4];
#pragma unroll
        for (int i = 0; i < 4; i++)
#pragma unroll
            for (int j = 0; j < 4; j++) acc[i][j] = 0.f;

        for (int k0 = 0; k0 < DIM; k0 += 32) {
            float4 a0  = *(const float4*)&A[(size_t)(m0 + ar) * DIM + k0 + ak];
            float4 a1  = *(const float4*)&A[(size_t)(m0 + ar) * DIM + k0 + ak + 4];
            float4 b0v = *(const float4*)&W[(size_t)(k0 + bk) * G3 + n0 + bc];
            float4 b1v = *(const float4*)&W[(size_t)(k0 + bk) * G3 + n0 + bc + 4];

            As[ak + 0][ar] = a0.x; As[ak + 1][ar] = a0.y;
            As[ak + 2][ar] = a0.z; As[ak + 3][ar] = a0.w;
            As[ak + 4][ar] = a1.x; As[ak + 5][ar] = a1.y;
            As[ak + 6][ar] = a1.z; As[ak + 7][ar] = a1.w;
            *(float4*)&Bs[bk][bc]     = b0v;
            *(float4*)&Bs[bk][bc + 4] = b1v;
            __syncthreads();

#pragma unroll
            for (int kk = 0; kk < 32; kk++) {
                const float av0 = As[kk][tx * 4 + 0];
                const float av1 = As[kk][tx * 4 + 1];
                const float av2 = As[kk][tx * 4 + 2];
                const float av3 = As[kk][tx * 4 + 3];
                const float4 bq = *(const float4*)&Bs[kk][ty * 4];
                acc[0][0] = fmaf(av0, bq.x, acc[0][0]);
                acc[1][0] = fmaf(av1, bq.x, acc[1][0]);
                acc[2][0] = fmaf(av2, bq.x, acc[2][0]);
                acc[3][0] = fmaf(av3, bq.x, acc[3][0]);
                acc[0][1] = fmaf(av0, bq.y, acc[0][1]);
                acc[1][1] = fmaf(av1, bq.y, acc[1][1]);
                acc[2][1] = fmaf(av2, bq.y, acc[2][1]);
                acc[3][1] = fmaf(av3, bq.y, acc[3][1]);
                acc[0][2] = fmaf(av0, bq.z, acc[0][2]);
                acc[1][2] = fmaf(av1, bq.z, acc[1][2]);
                acc[2][2] = fmaf(av2, bq.z, acc[2][2]);
                acc[3][2] = fmaf(av3, bq.z, acc[3][2]);
                acc[0][3] = fmaf(av0, bq.w, acc[0][3]);
                acc[1][3] = fmaf(av1, bq.w, acc[1][3]);
                acc[2][3] = fmaf(av2, bq.w, acc[2][3]);
                acc[3][3] = fmaf(av3, bq.w, acc[3][3]);
            }
            __syncthreads();
        }

        const int t  = bx * 2 + (tx >> 3);
        const int bb = (tx & 7) * 4;
#pragma unroll
        for (int ci = 0; ci < 4; ci++) {
            const int c = n0 + ty * 4 + ci;
            const float bv = bias[c];
            float4 v = make_float4(acc[0][ci] + bv, acc[1][ci] + bv,
                                   acc[2][ci] + bv, acc[3][ci] + bv);
            *(float4*)&g_X[((size_t)t * N2 + c) * BATCH + bb] = v;
        }

        __threadfence();      // publish g_X writes to GPU scope
        __syncthreads();      // all threads' stores issued before the count
        if (tid == 0) {
            asm volatile("red.release.gpu.global.add.u32 [%0], %1;"
                         :: "l"(&g_tcnt[bx]), "r"(1u) : "memory");
        }
    }
}

// ---------------------------------------------------------------------------
// ONE kernel: blocks 0..63 = layer-0 scan, 64..127 = layer-1 scan (1-step lag),
// blocks 128..191 = gemm workers (overlapped; scan polls g_tcnt per t).
// Flags are monotonic across replays: base = g_run * per-run-final.
// ---------------------------------------------------------------------------
__global__ __launch_bounds__(256, 2) void fused_all(
    const float* __restrict__ input,  // [T*B, 256]
    const float* __restrict__ Whh0,   // [256,768]
    const float* __restrict__ Whh1,   // [256,768]
    const float* __restrict__ Wih0,   // [256,768]
    const float* __restrict__ Wih1,   // [256,768]
    const float* __restrict__ b0,     // [768]
    const float* __restrict__ b1,     // [768]
    const int*   __restrict__ length, // [32] int32
    float* __restrict__ out1,         // [T,B,H]
    float* __restrict__ hn)           // [2,B,H]
{
    extern __shared__ float smem[];
    const int bid = blockIdx.x;

    if (bid >= NBLK) {                 // ---- GEMM worker path ----
        gemm_worker(bid - NBLK, input, Wih0, b0, smem);
        return;
    }

    // ---- persistent scan path ----
    float* hs    = smem;               // 512*32 floats (chunk-swizzled)
    float* red   = smem + N2 * BATCH;  // [64][34]
    float* out_s = red + 64 * 34;      // [32][4]
    float4*     hs4 = (float4*)hs;
    const ulonglong2* hsU = (const ulonglong2*)hs;

    const int tid   = threadIdx.x;
    const int layer = bid >> 6;
    const int jb    = (bid & 63) * 4;

    const int rg   = tid & 3;
    const int cg   = (tid >> 2) & 1;
    const int ks   = tid >> 3;
    const int warp = tid >> 5;
    const int gr   = tid & 31;
    const int gp   = tid >> 5;
    const int colbase = jb + cg * HID;
    const int swz  = layer ? (ks & 3) : ((ks >> 1) & 3);

    const int len_r = length[gr];
    int Lmax = 0;
#pragma unroll 8
    for (int r = 0; r < BATCH; r++) Lmax = max(Lmax, length[r]);

    // monotonic flag bases (per-run finals: L0 = Lmax, L1 = Lmax+1)
    const unsigned R       = *(volatile unsigned*)&g_run;
    const unsigned fbase0  = R * (unsigned)Lmax;
    const unsigned fbase1  = R * (unsigned)(Lmax + 1);
    const unsigned mybase  = layer ? fbase1 : fbase0;
    const unsigned pollbase = (tid < 64) ? fbase0 : fbase1;   // for tid<128
    const unsigned tbase   = R * 8u;                          // tcnt per-bx base

    // ---- weights in registers ----
    float w[4][16];
    if (layer == 0) {
#pragma unroll
        for (int ci = 0; ci < 4; ci++)
#pragma unroll
            for (int kk = 0; kk < 8; kk++)
                w[ci][kk] = Whh0[(size_t)(ks * 8 + kk) * G3 + colbase + ci];
#pragma unroll
        for (int ci = 0; ci < 4; ci++)
#pragma unroll
            for (int kk = 8; kk < 16; kk++) w[ci][kk] = 0.f;
    } else {
        const float* W = (ks < 16) ? Whh1 : Wih1;
        const int kb0 = (ks & 15) * 16;
#pragma unroll
        for (int ci = 0; ci < 4; ci++)
#pragma unroll
            for (int kk = 0; kk < 16; kk++)
                w[ci][kk] = W[(size_t)(kb0 + kk) * G3 + colbase + ci];
    }

    float bh = 0.f, bt = 0.f;
    if (layer && gp < 4) {
        bh = b1[jb + gp];
        bt = b1[HID + jb + gp];
    }

    // init out_s (used for tail fill even if no iterations run)
    for (int idx = tid; idx < BATCH * 4; idx += 256) out_s[idx] = 0.f;

    float hlast = 0.f;
    const int imax = layer ? Lmax : (Lmax - 1);

    for (int i = 0; i <= imax; i++) {
        const int  t   = layer ? (i - 1) : i;
        const bool act = layer ? (i >= 1) : true;

        // ---- wait phase ----
        if (i > 0 && tid < NBLK) {
            const int tgt = (layer || tid < 64) ? i : (i - 2);
            if (tgt > 0) {
                const unsigned target = pollbase + (unsigned)tgt;
                unsigned v;
                do {
                    asm volatile("ld.acquire.gpu.global.u32 %0, [%1];"
                                 : "=r"(v) : "l"(&g_flag[tid * 8]) : "memory");
                } while ((int)(v - target) < 0);
            }
        }
        if (!layer && tid == 128) {   // gemm progress for this timestep
            const unsigned target = tbase + 8u;
            unsigned v;
            do {
                asm volatile("ld.acquire.gpu.global.u32 %0, [%1];"
                             : "=r"(v) : "l"(&g_tcnt[i >> 1]) : "memory");
            } while ((int)(v - target) < 0);
        }
        __syncthreads();

        if (act) {
            // prefetch layer-0 x-term (latency hides behind staging + dot)
            float xh = 0.f, xt = 0.f;
            if (!layer && gp < 4) {
                const size_t bo = ((size_t)t * N2 + jb + gp) * BATCH + gr;
                xh = __ldg(&g_X[bo]);
                xt = __ldg(&g_X[bo + (size_t)HID * BATCH]);
            }

            // ---- stage h into swizzled smem ----
            const bool synth = layer ? (i == 1) : (i == 0);  // first step: h=0
            if (synth) {
                const float4 z = make_float4(0.f, 0.f, 0.f, 0.f);
                for (int idx = tid; idx < 2048; idx += 256) hs4[idx] = z;
            } else {
                const float4* srcA = (const float4*)(layer ? g_h1[(i + 1) & 1]
                                                           : g_h0[i & 3]);
                for (int idx = tid; idx < 2048; idx += 256) {
                    const int k = idx >> 3, c = idx & 7;
                    hs4[k * 8 + (c ^ ((k >> 4) & 3))] = __ldcg(srcA + idx);
                }
            }
            if (layer) {   // lagged h0 (x-term source), always real data
                const float4* srcX = (const float4*)g_h0[i & 3];
                for (int idx = tid; idx < 2048; idx += 256) {
                    const int k = 256 + (idx >> 3), c = idx & 7;
                    hs4[k * 8 + (c ^ ((k >> 4) & 3))] = __ldcg(srcX + idx);
                }
            }
            __syncthreads();

            // ---- packed dot ----
            unsigned long long acc[4][4];
#pragma unroll
            for (int ci = 0; ci < 4; ci++)
#pragma unroll
                for (int p = 0; p < 4; p++) acc[ci][p] = 0ull;

            if (layer) dot_slice<16>(hsU, w, ks * 16, rg, swz, acc);
            else       dot_slice<8>(hsU, w, ks * 8,  rg, swz, acc);

#pragma unroll
            for (int ci = 0; ci < 4; ci++)
#pragma unroll
                for (int p = 0; p < 4; p++) {
                    unsigned long long v = acc[ci][p];
                    v = add2(v, __shfl_xor_sync(0xffffffffu, v, 8));
                    v = add2(v, __shfl_xor_sync(0xffffffffu, v, 16));
                    acc[ci][p] = v;
                }
            if ((tid & 24) == 0) {
#pragma unroll
                for (int ci = 0; ci < 4; ci++)
#pragma unroll
                    for (int p = 0; p < 4; p++)
                        *(unsigned long long*)&red[(warp * 8 + cg * 4 + ci) * 34
                                                   + rg * 8 + 2 * p] = acc[ci][p];
            }
            __syncthreads();

            // ---- final reduce fused with gates ----
            if (gp < 4) {
                float sh = 0.f, stt = 0.f;
#pragma unroll
                for (int wp = 0; wp < 8; wp++) {
                    sh  += red[(wp * 8 + gp)     * 34 + gr];
                    stt += red[(wp * 8 + gp + 4) * 34 + gr];
                }
                const int j = jb + gp;
                const float ph = sh  + (layer ? bh : xh);
                const float pt = stt + (layer ? bt : xt);
                const float hprev = hs[j * 32 +
                    ((((unsigned)gr >> 2) ^ ((j >> 4) & 3)) << 2) + (gr & 3)];
                const float tg    = 1.f / (1.f + __expf(-pt));
                const float cgate = 1.f / (1.f + __expf(-tg));   // bug-faithful
                const float st    = tanhf(ph) * tg + hprev * cgate;
                const float hnew  = (t < len_r) ? st : hprev;
                hlast = hnew;
                if (layer) {
                    g_h1[i & 1][j * BATCH + gr] = hnew;
                    out_s[gr * 4 + gp] = hnew;
                } else {
                    g_h0[(i + 1) & 3][j * BATCH + gr] = hnew;
                }
            }
        }

        // ---- publish progress ----
        __syncthreads();
        if (tid == 0) {
            asm volatile("st.release.gpu.global.u32 [%0], %1;"
                         :: "l"(&g_flag[bid * 8]), "r"(mybase + (unsigned)(i + 1))
                         : "memory");
        }

        // output write off the critical path
        if (layer && act && tid < 32) {
            const float4 v = *(const float4*)&out_s[tid * 4];
            *(float4*)&out1[((size_t)t * BATCH + tid) * HID + jb] = v;
        }
    }

    // ---- epilogue: hn + frozen-tail fill ----
    if (gp < 4) {
        const int j = jb + gp;
        if (layer) hn[BATCH * HID + gr * HID + j] = hlast;
        else       hn[gr * HID + j] = hlast;
    }
    if (layer) {
        __syncthreads();   // out_s final
        const int ntail = (T_LEN - Lmax) * BATCH;
        for (int idx = tid; idx < ntail; idx += 256) {
            const int tt = Lmax + (idx >> 5), r = idx & 31;
            *(float4*)&out1[((size_t)tt * BATCH + r) * HID + jb] =
                *(const float4*)&out_s[r * 4];
        }
    }

    // ---- run-completion: block 0 advances the epoch ----
    if (bid == 0) {
        if (tid < NBLK) {
            const unsigned target = (tid < 64) ? (fbase0 + (unsigned)Lmax)
                                               : (fbase1 + (unsigned)(Lmax + 1));
            unsigned v;
            do {
                asm volatile("ld.acquire.gpu.global.u32 %0, [%1];"
                             : "=r"(v) : "l"(&g_flag[tid * 8]) : "memory");
            } while ((int)(v - target) < 0);
        }
        __syncthreads();
        if (tid == 0) *(volatile unsigned*)&g_run = R + 1u;
    }
}

// ---------------------------------------------------------------------------
extern "C" void kernel_launch(void* const* d_in, const int* in_sizes, int n_in,
                              void* d_out, int out_size) {
    const float* input  = (const float*)d_in[0];
    const int*   length = (const int*)d_in[1];
    const float* Wih0   = (const float*)d_in[2];
    const float* Whh0   = (const float*)d_in[3];
    const float* b0     = (const float*)d_in[4];
    const float* Wih1   = (const float*)d_in[5];
    const float* Whh1   = (const float*)d_in[6];
    const float* b1     = (const float*)d_in[7];

    float* out1 = (float*)d_out;
    float* hn   = (float*)d_out + (size_t)T_LEN * BATCH * HID;

    const int smem_bytes = (N2 * BATCH + 64 * 34 + BATCH * 4) * 4;
    static bool attr_set = false;
    if (!attr_set) {
        cudaFuncSetAttribute(fused_all, cudaFuncAttributeMaxDynamicSharedMemorySize,
                             smem_bytes);
        attr_set = true;
    }

    fused_all<<<NBLK + NWORK, 256, smem_bytes>>>(
        input, Whh0, Whh1, Wih0, Wih1, b0, b1, length, out1, hn);
}

// round 7
// speedup vs baseline: 1.9305x; 1.0543x over previous
#include <cuda_runtime.h>
#include <cstdint>

// Problem constants
#define T_LEN 2048
#define BATCH 32
#define HID   256
#define G3    768    // 3H (weight leading dim)
#define N2    512    // only first 2H pre-columns matter (c_pre is dead)
#define NSCAN 64     // merged dual-layer scan blocks
#define NTOT  148    // total grid (<= 148 SMs -> all co-resident, 1/SM)
#define NWORK (NTOT - NSCAN)   // 84 gemm workers
#define NTILE 8192   // 1024 t-pair rows * 8 col tiles

// ---------------------------------------------------------------------------
// Device scratch (allocations forbidden -> __device__ globals)
// ---------------------------------------------------------------------------
__device__ float g_X[(size_t)T_LEN * N2 * BATCH];  // x@Wih0+b0, [t][c(512)][b(32)]
__device__ float g_h0[2][HID * BATCH];             // h0(t) in slot t&1, layout [k][r]
__device__ float g_h1[2][HID * BATCH];             // h1(t) in slot t&1
__device__ unsigned g_flag[NSCAN * 8];             // monotonic progress flags
__device__ unsigned g_tcnt[T_LEN / 2];             // gemm tile counters (8/run/row)
__device__ unsigned g_run;                         // completed-run epoch

// ---------------------------------------------------------------------------
// Packed f32x2 helpers (FFMA2 via PTX only on sm_103a)
// ---------------------------------------------------------------------------
__device__ __forceinline__ unsigned long long pack2(float v) {
    unsigned long long r;
    asm("mov.b64 %0, {%1, %1};" : "=l"(r) : "f"(v));
    return r;
}
__device__ __forceinline__ void fma2(unsigned long long& d,
                                     unsigned long long a, unsigned long long b) {
    asm("fma.rn.f32x2 %0, %1, %2, %0;" : "+l"(d) : "l"(a), "l"(b));
}
__device__ __forceinline__ unsigned long long add2(unsigned long long a,
                                                   unsigned long long b) {
    unsigned long long r;
    asm("add.rn.f32x2 %0, %1, %2;" : "=l"(r) : "l"(a), "l"(b));
    return r;
}

// ---------------------------------------------------------------------------
// GEMM worker: grid-strided 64x64x256 tiles of g_X = input @ Wih0[:,:512]+b0.
// ---------------------------------------------------------------------------
__device__ void gemm_worker(int wb, const float* __restrict__ A,
                            const float* __restrict__ W,
                            const float* __restrict__ bias,
                            float* smem, int Lmax)
{
    float (*As)[65] = (float(*)[65])smem;
    float (*Bs)[64] = (float(*)[64])(smem + 32 * 65);

    const int tid = threadIdx.x;
    const int tx  = tid & 15;
    const int ty  = tid >> 4;
    const int ar  = tid >> 2;
    const int ak  = (tid & 3) * 8;
    const int bk  = tid >> 3;
    const int bc  = (tid & 7) * 8;

    for (int n = wb; n < NTILE; n += NWORK) {
        const int bx = n >> 3;
        if (2 * bx >= Lmax) break;       // rows t >= Lmax never consumed
        const int m0 = bx * 64;
        const int n0 = (n & 7) * 64;

        float acc[4][4];
#pragma unroll
        for (int i = 0; i < 4; i++)
#pragma unroll
            for (int j = 0; j < 4; j++) acc[i][j] = 0.f;

        for (int k0 = 0; k0 < 256; k0 += 32) {
            float4 a0  = *(const float4*)&A[(size_t)(m0 + ar) * 256 + k0 + ak];
            float4 a1  = *(const float4*)&A[(size_t)(m0 + ar) * 256 + k0 + ak + 4];
            float4 b0v = *(const float4*)&W[(size_t)(k0 + bk) * G3 + n0 + bc];
            float4 b1v = *(const float4*)&W[(size_t)(k0 + bk) * G3 + n0 + bc + 4];

            As[ak + 0][ar] = a0.x; As[ak + 1][ar] = a0.y;
            As[ak + 2][ar] = a0.z; As[ak + 3][ar] = a0.w;
            As[ak + 4][ar] = a1.x; As[ak + 5][ar] = a1.y;
            As[ak + 6][ar] = a1.z; As[ak + 7][ar] = a1.w;
            *(float4*)&Bs[bk][bc]     = b0v;
            *(float4*)&Bs[bk][bc + 4] = b1v;
            __syncthreads();

#pragma unroll
            for (int kk = 0; kk < 32; kk++) {
                const float av0 = As[kk][tx * 4 + 0];
                const float av1 = As[kk][tx * 4 + 1];
                const float av2 = As[kk][tx * 4 + 2];
                const float av3 = As[kk][tx * 4 + 3];
                const float4 bq = *(const float4*)&Bs[kk][ty * 4];
                acc[0][0] = fmaf(av0, bq.x, acc[0][0]);
                acc[1][0] = fmaf(av1, bq.x, acc[1][0]);
                acc[2][0] = fmaf(av2, bq.x, acc[2][0]);
                acc[3][0] = fmaf(av3, bq.x, acc[3][0]);
                acc[0][1] = fmaf(av0, bq.y, acc[0][1]);
                acc[1][1] = fmaf(av1, bq.y, acc[1][1]);
                acc[2][1] = fmaf(av2, bq.y, acc[2][1]);
                acc[3][1] = fmaf(av3, bq.y, acc[3][1]);
                acc[0][2] = fmaf(av0, bq.z, acc[0][2]);
                acc[1][2] = fmaf(av1, bq.z, acc[1][2]);
                acc[2][2] = fmaf(av2, bq.z, acc[2][2]);
                acc[3][2] = fmaf(av3, bq.z, acc[3][2]);
                acc[0][3] = fmaf(av0, bq.w, acc[0][3]);
                acc[1][3] = fmaf(av1, bq.w, acc[1][3]);
                acc[2][3] = fmaf(av2, bq.w, acc[2][3]);
                acc[3][3] = fmaf(av3, bq.w, acc[3][3]);
            }
            __syncthreads();
        }

        const int t  = bx * 2 + (tx >> 3);
        const int bb = (tx & 7) * 4;
#pragma unroll
        for (int ci = 0; ci < 4; ci++) {
            const int c = n0 + ty * 4 + ci;
            const float bv = bias[c];
            float4 v = make_float4(acc[0][ci] + bv, acc[1][ci] + bv,
                                   acc[2][ci] + bv, acc[3][ci] + bv);
            *(float4*)&g_X[((size_t)t * N2 + c) * BATCH + bb] = v;
        }

        __threadfence();
        __syncthreads();
        if (tid == 0) {
            asm volatile("red.release.gpu.global.add.u32 [%0], %1;"
                         :: "l"(&g_tcnt[bx]), "r"(1u) : "memory");
        }
    }
}

// ---------------------------------------------------------------------------
// ONE kernel, 148 blocks (1 per SM):
//   blocks 0..63  : merged dual-layer scan (warps 0-3: layer-0, 4-7: layer-1)
//   blocks 64..147: gemm workers
// Per round i: layer-0 computes h0(i) (i<Lmax), layer-1 computes h1(i-1) (i>=1).
// Staged vector = [h1(i-2) ; h0(i-1)] serves BOTH layers.
// ---------------------------------------------------------------------------
__global__ __launch_bounds__(256, 1) void fused_all(
    const float* __restrict__ input,  // [T*B, 256]
    const float* __restrict__ Whh0,   // [256,768]
    const float* __restrict__ Whh1,   // [256,768]
    const float* __restrict__ Wih0,   // [256,768]
    const float* __restrict__ Wih1,   // [256,768]
    const float* __restrict__ b0,     // [768]
    const float* __restrict__ b1,     // [768]
    const int*   __restrict__ length, // [32] int32
    float* __restrict__ out1,         // [T,B,H]
    float* __restrict__ hn)           // [2,B,H]
{
    extern __shared__ float smem[];
    const int bid = blockIdx.x;
    const int tid = threadIdx.x;

    int Lmax = 0;
#pragma unroll 8
    for (int r = 0; r < BATCH; r++) Lmax = max(Lmax, length[r]);

    if (bid >= NSCAN) {                       // ---- GEMM worker path ----
        gemm_worker(bid - NSCAN, input, Wih0, b0, smem, Lmax);
        return;
    }

    // ---- scan path ----
    float* hs    = smem;               // [512 k][32 r] chunk-swizzled (64KB)
    float* red   = smem + N2 * BATCH;  // [2 grp][16 part][8 col][34]
    float* out_s = red + 2 * 16 * 8 * 34;  // [32][4]
    float4* hs4  = (float4*)hs;
    const ulonglong2* hsU = (const ulonglong2*)hs;

    const int grp  = tid >> 7;         // 0 = layer-0, 1 = layer-1
    const int wg   = (tid >> 5) & 3;   // warp in group (= gate col)
    const int lane = tid & 31;         // gate row (batch)
    const int rg   = lane & 1;         // row half (16 rows each)
    const int cg   = (lane >> 1) & 1;  // pre-col half (h_pre / t_pre)
    const int ks   = wg * 8 + (lane >> 2);   // k-slice 0..31
    const int jb   = bid * 4;
    const int colbase = jb + cg * HID;
    const int swz  = grp ? (ks & 3) : ((ks >> 1) & 3);

    const int len_r = length[lane];

    const unsigned R     = *(volatile unsigned*)&g_run;
    const unsigned fbase = R * (unsigned)(Lmax + 1);
    const unsigned tbase = R * 8u;

    // ---- weights in registers ----
    float w[4][16];
    if (grp == 0) {     // layer-0: K=256 (upper half of staged vec), 8 k/slice
#pragma unroll
        for (int ci = 0; ci < 4; ci++) {
#pragma unroll
            for (int kk = 0; kk < 8; kk++)
                w[ci][kk] = Whh0[(size_t)(ks * 8 + kk) * G3 + colbase + ci];
#pragma unroll
            for (int kk = 8; kk < 16; kk++) w[ci][kk] = 0.f;
        }
    } else {            // layer-1: K=512 = [Whh1 ; Wih1], 16 k/slice
        const float* W = (ks < 16) ? Whh1 : Wih1;
        const int kb0 = (ks & 15) * 16;
#pragma unroll
        for (int ci = 0; ci < 4; ci++)
#pragma unroll
            for (int kk = 0; kk < 16; kk++)
                w[ci][kk] = W[(size_t)(kb0 + kk) * G3 + colbase + ci];
    }

    float bh = 0.f, bt = 0.f;
    if (grp) { bh = b1[jb + wg]; bt = b1[HID + jb + wg]; }

    for (int idx = tid; idx < BATCH * 4; idx += 256) out_s[idx] = 0.f;

    float hlast = 0.f;

    for (int i = 0; i <= Lmax; i++) {
        const bool act0 = (i < Lmax);      // layer-0 step t=i
        const bool act1 = (i >= 1);        // layer-1 step t=i-1

        // ---- wait: all 64 flags >= i, plus gemm row i ready ----
        if (i > 0 && tid < NSCAN) {
            const unsigned target = fbase + (unsigned)i;
            unsigned v;
            do {
                asm volatile("ld.acquire.gpu.global.u32 %0, [%1];"
                             : "=r"(v) : "l"(&g_flag[tid * 8]) : "memory");
            } while ((int)(v - target) < 0);
        }
        if (tid == 64 && act0) {
            const unsigned target = tbase + 8u;
            unsigned v;
            do {
                asm volatile("ld.acquire.gpu.global.u32 %0, [%1];"
                             : "=r"(v) : "l"(&g_tcnt[i >> 1]) : "memory");
            } while ((int)(v - target) < 0);
        }
        __syncthreads();

        // ---- prefetch layer-0 x-term (latency hides behind stage + dot) ----
        float xh = 0.f, xt = 0.f;
        if (grp == 0 && act0) {
            const size_t bo = ((size_t)i * N2 + jb + wg) * BATCH + lane;
            xh = __ldg(&g_X[bo]);
            xt = __ldg(&g_X[bo + (size_t)HID * BATCH]);
        }

        // ---- stage [h1(i-2) ; h0(i-1)] into swizzled smem ----
        if (i >= 2) {
            const float4* s = (const float4*)g_h1[i & 1];   // h1(i-2): slot (i-2)&1
            for (int idx = tid; idx < 2048; idx += 256) {
                const int k = idx >> 3, c = idx & 7;
                hs4[k * 8 + (c ^ ((k >> 4) & 3))] = __ldcg(s + idx);
            }
        } else {
            const float4 z = make_float4(0.f, 0.f, 0.f, 0.f);
            for (int idx = tid; idx < 2048; idx += 256) hs4[idx] = z;
        }
        if (i >= 1) {
            const float4* s = (const float4*)g_h0[(i - 1) & 1];
            for (int idx = tid; idx < 2048; idx += 256) {
                const int k = 256 + (idx >> 3), c = idx & 7;
                hs4[k * 8 + (c ^ ((k >> 4) & 3))] = __ldcg(s + idx);
            }
        } else {
            const float4 z = make_float4(0.f, 0.f, 0.f, 0.f);
            for (int idx = tid; idx < 2048; idx += 256) hs4[2048 + idx] = z;
        }
        __syncthreads();

        // ---- packed dot over this thread's slice (16 rows, 4 pre-cols) ----
        const bool myact = grp ? act1 : act0;
        unsigned long long acc[4][8];
        if (myact) {
#pragma unroll
            for (int ci = 0; ci < 4; ci++)
#pragma unroll
                for (int p = 0; p < 8; p++) acc[ci][p] = 0ull;

            if (grp == 0) {
#pragma unroll
                for (int kk = 0; kk < 8; kk++) {
                    const int b4 = (256 + ks * 8 + kk) * 8;
                    const ulonglong2 c0 = hsU[b4 + ((rg * 4 + 0) ^ swz)];
                    const ulonglong2 c1 = hsU[b4 + ((rg * 4 + 1) ^ swz)];
                    const ulonglong2 c2 = hsU[b4 + ((rg * 4 + 2) ^ swz)];
                    const ulonglong2 c3 = hsU[b4 + ((rg * 4 + 3) ^ swz)];
#pragma unroll
                    for (int ci = 0; ci < 4; ci++) {
                        const unsigned long long w2 = pack2(w[ci][kk]);
                        fma2(acc[ci][0], c0.x, w2); fma2(acc[ci][1], c0.y, w2);
                        fma2(acc[ci][2], c1.x, w2); fma2(acc[ci][3], c1.y, w2);
                        fma2(acc[ci][4], c2.x, w2); fma2(acc[ci][5], c2.y, w2);
                        fma2(acc[ci][6], c3.x, w2); fma2(acc[ci][7], c3.y, w2);
                    }
                }
            } else {
#pragma unroll
                for (int kk = 0; kk < 16; kk++) {
                    const int b4 = (ks * 16 + kk) * 8;
                    const ulonglong2 c0 = hsU[b4 + ((rg * 4 + 0) ^ swz)];
                    const ulonglong2 c1 = hsU[b4 + ((rg * 4 + 1) ^ swz)];
                    const ulonglong2 c2 = hsU[b4 + ((rg * 4 + 2) ^ swz)];
                    const ulonglong2 c3 = hsU[b4 + ((rg * 4 + 3) ^ swz)];
#pragma unroll
                    for (int ci = 0; ci < 4; ci++) {
                        const unsigned long long w2 = pack2(w[ci][kk]);
                        fma2(acc[ci][0], c0.x, w2); fma2(acc[ci][1], c0.y, w2);
                        fma2(acc[ci][2], c1.x, w2); fma2(acc[ci][3], c1.y, w2);
                        fma2(acc[ci][4], c2.x, w2); fma2(acc[ci][5], c2.y, w2);
                        fma2(acc[ci][6], c3.x, w2); fma2(acc[ci][7], c3.y, w2);
                    }
                }
            }

            // one shuffle round (xor 4 = ks bit 0), then smem partials
#pragma unroll
            for (int ci = 0; ci < 4; ci++)
#pragma unroll
                for (int p = 0; p < 8; p++)
                    acc[ci][p] = add2(acc[ci][p],
                                      __shfl_xor_sync(0xffffffffu, acc[ci][p], 4));
            if ((lane & 4) == 0) {
                const int part = wg * 4 + (lane >> 3);
#pragma unroll
                for (int ci = 0; ci < 4; ci++)
#pragma unroll
                    for (int p = 0; p < 8; p++) {
                        const int row = rg * 16 + (p >> 1) * 4 + (p & 1) * 2;
                        *(unsigned long long*)&red[((grp * 16 + part) * 8
                            + cg * 4 + ci) * 34 + row] = acc[ci][p];
                    }
            }
        }
        __syncthreads();

        // ---- final reduce (16 partials) fused with gates ----
        if (myact) {
            float sh = 0.f, st = 0.f;
#pragma unroll
            for (int part = 0; part < 16; part++) {
                sh += red[((grp * 16 + part) * 8 + wg)     * 34 + lane];
                st += red[((grp * 16 + part) * 8 + wg + 4) * 34 + lane];
            }
            const int j  = jb + wg;
            const int t  = grp ? (i - 1) : i;
            const float ph = sh + (grp ? bh : xh);
            const float pt = st + (grp ? bt : xt);
            const int   k0 = grp ? j : (256 + j);
            const float hprev = hs[k0 * 32 +
                (((lane >> 2) ^ ((k0 >> 4) & 3)) << 2) + (lane & 3)];
            const float tg    = 1.f / (1.f + __expf(-pt));
            const float cgate = 1.f / (1.f + __expf(-tg));  // bug-faithful
            const float sv    = tanhf(ph) * tg + hprev * cgate;
            const float hnew  = (t < len_r) ? sv : hprev;
            hlast = hnew;
            if (grp) {
                g_h1[(i - 1) & 1][j * BATCH + lane] = hnew;
                out_s[lane * 4 + wg] = hnew;
            } else {
                g_h0[i & 1][j * BATCH + lane] = hnew;
            }
        }
        __syncthreads();

        // ---- publish (release orders prior writes via the barrier chain) ----
        if (tid == 0) {
            asm volatile("st.release.gpu.global.u32 [%0], %1;"
                         :: "l"(&g_flag[bid * 8]), "r"(fbase + (unsigned)(i + 1))
                         : "memory");
        }

        // ---- out1 write off the critical path ----
        if (grp == 1 && act1 && tid < 160) {   // threads 128..159
            const int r = tid - 128;
            const float4 v = *(const float4*)&out_s[r * 4];
            *(float4*)&out1[((size_t)(i - 1) * BATCH + r) * HID + jb] = v;
        }
    }

    // ---- epilogue: hn + frozen-tail fill ----
    {
        const int j = jb + wg;
        if (grp) hn[BATCH * HID + lane * HID + j] = hlast;
        else     hn[lane * HID + j] = hlast;
    }
    __syncthreads();
    {
        const int ntail = (T_LEN - Lmax) * BATCH;
        for (int idx = tid; idx < ntail; idx += 256) {
            const int tt = Lmax + (idx >> 5), r = idx & 31;
            *(float4*)&out1[((size_t)tt * BATCH + r) * HID + jb] =
                *(const float4*)&out_s[r * 4];
        }
    }

    // ---- run-completion: block 0 advances the epoch ----
    if (bid == 0) {
        if (tid < NSCAN) {
            const unsigned target = fbase + (unsigned)(Lmax + 1);
            unsigned v;
            do {
                asm volatile("ld.acquire.gpu.global.u32 %0, [%1];"
                             : "=r"(v) : "l"(&g_flag[tid * 8]) : "memory");
            } while ((int)(v - target) < 0);
        }
        __syncthreads();
        if (tid == 0) *(volatile unsigned*)&g_run = R + 1u;
    }
}

// ---------------------------------------------------------------------------
extern "C" void kernel_launch(void* const* d_in, const int* in_sizes, int n_in,
                              void* d_out, int out_size) {
    const float* input  = (const float*)d_in[0];
    const int*   length = (const int*)d_in[1];
    const float* Wih0   = (const float*)d_in[2];
    const float* Whh0   = (const float*)d_in[3];
    const float* b0     = (const float*)d_in[4];
    const float* Wih1   = (const float*)d_in[5];
    const float* Whh1   = (const float*)d_in[6];
    const float* b1     = (const float*)d_in[7];

    float* out1 = (float*)d_out;
    float* hn   = (float*)d_out + (size_t)T_LEN * BATCH * HID;

    const int smem_bytes = (N2 * BATCH + 2 * 16 * 8 * 34 + BATCH * 4) * 4;
    static bool attr_set = false;
    if (!attr_set) {
        cudaFuncSetAttribute(fused_all, cudaFuncAttributeMaxDynamicSharedMemorySize,
                             smem_bytes);
        attr_set = true;
    }

    fused_all<<<NTOT, 256, smem_bytes>>>(
        input, Whh0, Whh1, Wih0, Wih1, b0, b1, length, out1, hn);
}